// round 14
// baseline (speedup 1.0000x reference)
#include <cuda_runtime.h>
#include <cuda_fp16.h>

typedef unsigned int u32;

#define NT  256
#define BM  128
#define BN  64
#define Dh  128
#define SEQ 2048
#define NIT (SEQ / BN)
#define NBH 64
#define LOG2E 1.44269504088896340736f

// ---- smem byte layout (main kernel) ----
#define QH_OFF 0
#define QL_OFF 32768
#define K_OFF  65536            // 3 bufs x 32768 (hi 16K + lo 16K)
#define V_OFF  163840           // 3 bufs x 16384 (hi only)
#define MBD_OFF 212992          // 3 data mbarriers x 8B
#define MBE_OFF 213016          // 3 empty mbarriers x 8B
#define SMEM_BYTES 213248

// ---- global scratch: pre-split f16 K/V images in exact swizzled smem layout ----
__device__ u32 gKsc[NBH * 32 * 8192];    // per (bh,ktile): 16KB hi + 16KB lo
__device__ u32 gVsc[NBH * 32 * 4096];    // per (bh,ktile): 16KB hi

static __device__ __forceinline__ u32 cvta_smem(const void* p) {
    u32 a;
    asm("{ .reg .u64 t; cvta.to.shared.u64 t, %1; cvt.u32.u64 %0, t; }" : "=r"(a) : "l"(p));
    return a;
}
static __device__ __forceinline__ u32 swoff(int row, int ch) {
    return (u32)(row * 256 + ((ch ^ (row & 7)) << 4));
}
static __device__ __forceinline__ float ex2(float x) {
    float y; asm("ex2.approx.f32 %0, %1;" : "=f"(y) : "f"(x)); return y;
}
static __device__ __forceinline__ u32 pack2(float x0, float x1) {
    __half2 h = __floats2half2_rn(x0, x1);
    return *(u32*)&h;
}
static __device__ __forceinline__ void split2(float x0, float x1, u32& hi, u32& lo) {
    __half2 h = __floats2half2_rn(x0, x1);
    float2  b = __half22float2(h);
    __half2 l = __floats2half2_rn(x0 - b.x, x1 - b.y);
    hi = *(u32*)&h; lo = *(u32*)&l;
}

static __device__ __forceinline__ void ldm4(u32 addr, u32& r0, u32& r1, u32& r2, u32& r3) {
    asm volatile("ldmatrix.sync.aligned.m8n8.x4.shared.b16 {%0,%1,%2,%3}, [%4];"
                 : "=r"(r0), "=r"(r1), "=r"(r2), "=r"(r3) : "r"(addr));
}
static __device__ __forceinline__ void ldm4t(u32 addr, u32& r0, u32& r1, u32& r2, u32& r3) {
    asm volatile("ldmatrix.sync.aligned.m8n8.x4.trans.shared.b16 {%0,%1,%2,%3}, [%4];"
                 : "=r"(r0), "=r"(r1), "=r"(r2), "=r"(r3) : "r"(addr));
}
static __device__ __forceinline__ void mma(float* d, u32 a0, u32 a1, u32 a2, u32 a3, u32 b0, u32 b1) {
    asm volatile("mma.sync.aligned.m16n8k16.row.col.f32.f16.f16.f32 "
                 "{%0,%1,%2,%3}, {%4,%5,%6,%7}, {%8,%9}, {%0,%1,%2,%3};"
                 : "+f"(d[0]), "+f"(d[1]), "+f"(d[2]), "+f"(d[3])
                 : "r"(a0), "r"(a1), "r"(a2), "r"(a3), "r"(b0), "r"(b1));
}
#define CP16(dst, src) \
    asm volatile("cp.async.cg.shared.global [%0], [%1], 16;" :: "r"(dst), "l"(src))
// .noinc is load-bearing (round-11 deadlock lesson).
#define CP_MBAR_ARRIVE(mb) \
    asm volatile("cp.async.mbarrier.arrive.noinc.shared.b64 [%0];" :: "r"(mb) : "memory")
#define MBAR_ARRIVE(mb) \
    asm volatile("mbarrier.arrive.shared.b64 _, [%0];" :: "r"(mb) : "memory")
#define MBAR_INIT(mb, c) \
    asm volatile("mbarrier.init.shared.b64 [%0], %1;" :: "r"(mb), "r"(c) : "memory")
#define MBAR_WAIT(mb, par) do { \
    u32 _done = 0; \
    while (!_done) { \
        asm volatile("{\n\t.reg .pred p;\n\t" \
            "mbarrier.test_wait.parity.shared.b64 p, [%1], %2;\n\t" \
            "selp.u32 %0, 1, 0, p;\n\t}" \
            : "=r"(_done) : "r"(mb), "r"((u32)(par)) : "memory"); \
    } \
} while (0)

// ============ prep kernel: split K/V f32 -> f16 hi/lo swizzled images ============
__global__ __launch_bounds__(NT, 4)
void prep_kernel(const float* __restrict__ kg, const float* __restrict__ vg)
{
    const int t = blockIdx.x;        // 0..31 (64-row tile)
    const int bh = blockIdx.y;       // 0..63
    const int tid = threadIdx.x;
    const size_t base = (size_t)bh * SEQ * Dh + (size_t)t * 64 * Dh;

    {
        const float* src = kg + base;
        u32* dh = gKsc + (size_t)(bh * 32 + t) * 8192;
        u32* dl = dh + 4096;
        #pragma unroll
        for (int p = 0; p < 4; p++) {
            int idx = tid + p * 256;
            int row = idx >> 4, ch = idx & 15;
            const float* s = src + (size_t)row * Dh + ch * 8;
            float4 a = *(const float4*)s;
            float4 b = *(const float4*)(s + 4);
            u32 h0, l0, h1, l1, h2, l2, h3, l3;
            split2(a.x, a.y, h0, l0); split2(a.z, a.w, h1, l1);
            split2(b.x, b.y, h2, l2); split2(b.z, b.w, h3, l3);
            u32 off = swoff(row, ch) >> 2;
            *(uint4*)(dh + off) = make_uint4(h0, h1, h2, h3);
            *(uint4*)(dl + off) = make_uint4(l0, l1, l2, l3);
        }
    }
    {
        const float* src = vg + base;
        u32* dv = gVsc + (size_t)(bh * 32 + t) * 4096;
        #pragma unroll
        for (int p = 0; p < 4; p++) {
            int idx = tid + p * 256;
            int row = idx >> 4, ch = idx & 15;
            const float* s = src + (size_t)row * Dh + ch * 8;
            float4 a = *(const float4*)s;
            float4 b = *(const float4*)(s + 4);
            u32 off = swoff(row, ch) >> 2;
            *(uint4*)(dv + off) = make_uint4(pack2(a.x, a.y), pack2(a.z, a.w),
                                             pack2(b.x, b.y), pack2(b.z, b.w));
        }
    }
}

// ============ main kernel ============
__global__ __launch_bounds__(NT, 1)
void attn_hmma(const float* __restrict__ qg, const float* __restrict__ scg,
               float* __restrict__ og)
{
    extern __shared__ char sm[];
    const u32 smb = cvta_smem(sm);
    const int tid = threadIdx.x, lane = tid & 31, wid = tid >> 5;
    const bool producer = (tid >= 128);   // warps 4-7 own all cp.async traffic

    const int tile = blockIdx.x;
    const int bh   = blockIdx.y;
    const float* Qg = qg + (size_t)bh * SEQ * Dh + (size_t)tile * BM * Dh;
    float*       Og = og + (size_t)bh * SEQ * Dh + (size_t)tile * BM * Dh;
    const float scL = scg[bh] * LOG2E;

    const char* gK = (const char*)(gKsc + (size_t)(bh * 32) * 8192);
    const char* gV = (const char*)(gVsc + (size_t)(bh * 32) * 4096);

    // producer-thread copy of tile t into buf b3 (2x slices), arrive on data mbar
    auto issue_tile = [&](int t, int b3) {
        const int it = tid - 128;            // 0..127
        const char* nk = gK + (size_t)t * 32768;
        const char* nv = gV + (size_t)t * 16384;
        u32 kd = smb + K_OFF + b3 * 32768 + it * 16;
        u32 vd = smb + V_OFF + b3 * 16384 + it * 16;
        #pragma unroll
        for (int i = 0; i < 16; i++)
            CP16(kd + i * 2048, nk + it * 16 + i * 2048);
        #pragma unroll
        for (int i = 0; i < 8; i++)
            CP16(vd + i * 2048, nv + it * 16 + i * 2048);
        CP_MBAR_ARRIVE(smb + MBD_OFF + b3 * 8);
    };

    // ---- prologue ----
    if (tid == 0) {
        MBAR_INIT(smb + MBD_OFF + 0,  128);
        MBAR_INIT(smb + MBD_OFF + 8,  128);
        MBAR_INIT(smb + MBD_OFF + 16, 128);
        MBAR_INIT(smb + MBE_OFF + 0,  NT);
        MBAR_INIT(smb + MBE_OFF + 8,  NT);
        MBAR_INIT(smb + MBE_OFF + 16, NT);
    }
    __syncthreads();

    if (producer) issue_tile(0, 0);

    // convert Q (scale folded, split) while tile-0 copies fly
    #pragma unroll
    for (int p = 0; p < 8; p++) {
        int idx = tid + p * 256;
        int row = idx >> 4, ch = idx & 15;
        const float* s = Qg + (size_t)row * Dh + ch * 8;
        float4 a = *(const float4*)s;
        float4 b = *(const float4*)(s + 4);
        u32 h0, l0, h1, l1, h2, l2, h3, l3;
        split2(a.x * scL, a.y * scL, h0, l0); split2(a.z * scL, a.w * scL, h1, l1);
        split2(b.x * scL, b.y * scL, h2, l2); split2(b.z * scL, b.w * scL, h3, l3);
        u32 off = swoff(row, ch);
        *(uint4*)(sm + QH_OFF + off) = make_uint4(h0, h1, h2, h3);
        *(uint4*)(sm + QL_OFF + off) = make_uint4(l0, l1, l2, l3);
    }
    __syncthreads();   // Q visible to all warps

    // ---- per-warp state ----
    float oacc[16][4];
    #pragma unroll
    for (int f = 0; f < 16; f++)
        #pragma unroll
        for (int j = 0; j < 4; j++) oacc[f][j] = 0.f;
    float mA = -1e30f, mB = -1e30f, lA = 0.f, lB = 0.f;   // l: lane-partial

    const int wr0 = wid * 16;
    const int qrow = wr0 + (lane & 15);
    const int qchh = lane >> 4;
    const int kn   = (lane & 7) + ((lane >> 4) << 3);
    const int kchh = (lane >> 3) & 1;
    const int vkey = (lane & 7) + (((lane >> 3) & 1) << 3);
    const int vchh = lane >> 4;

    int b3 = 0, par = 0;   // tile n: buf b3 = n%3, data parity = (n/3)&1

    #pragma unroll 1
    for (int n = 0; n < NIT; n++) {
        // wait for tile n's copies (producers' slices) to land
        MBAR_WAIT(smb + MBD_OFF + b3 * 8, par);

        // producers: refill buf (n+1)%3 after its previous occupant (tile n-2)
        // is consumed by ALL warps (empty barrier), then issue tile n+1
        const int b3n = (b3 == 2) ? 0 : b3 + 1;
        if (producer && n + 1 < NIT) {
            const int t = n + 1, j = t / 3;
            if (j >= 1) MBAR_WAIT(smb + MBE_OFF + b3n * 8, (u32)((j - 1) & 1));
            issue_tile(t, b3n);
        }

        const u32 khb = smb + K_OFF + b3 * 32768;
        const u32 klb = khb + 16384;
        const u32 vhb = smb + V_OFF + b3 * 16384;

        // ---- S = (Qh+Ql)(Kh+Kl)^T, 3 products ----
        float sacc[8][4];
        #pragma unroll
        for (int f = 0; f < 8; f++)
            #pragma unroll
            for (int j = 0; j < 4; j++) sacc[f][j] = 0.f;

        #pragma unroll
        for (int kk = 0; kk < 8; kk++) {
            u32 qoff = swoff(qrow, kk * 2 + qchh);
            u32 qh0, qh1, qh2, qh3, ql0, ql1, ql2, ql3;
            ldm4(smb + QH_OFF + qoff, qh0, qh1, qh2, qh3);
            ldm4(smb + QL_OFF + qoff, ql0, ql1, ql2, ql3);
            #pragma unroll
            for (int jp = 0; jp < 4; jp++) {
                u32 koff = swoff(jp * 16 + kn, kk * 2 + kchh);
                u32 kb0, kb1, kb2, kb3, lb0, lb1, lb2, lb3;
                ldm4(khb + koff, kb0, kb1, kb2, kb3);
                ldm4(klb + koff, lb0, lb1, lb2, lb3);
                mma(sacc[jp * 2],     qh0, qh1, qh2, qh3, kb0, kb1);
                mma(sacc[jp * 2],     qh0, qh1, qh2, qh3, lb0, lb1);
                mma(sacc[jp * 2],     ql0, ql1, ql2, ql3, kb0, kb1);
                mma(sacc[jp * 2 + 1], qh0, qh1, qh2, qh3, kb2, kb3);
                mma(sacc[jp * 2 + 1], qh0, qh1, qh2, qh3, lb2, lb3);
                mma(sacc[jp * 2 + 1], ql0, ql1, ql2, ql3, kb2, kb3);
            }
        }

        // ---- phase 1: max scan, alpha, O-rescale (round-12 exact semantics) ----
        float rmaxA = -1e30f, rmaxB = -1e30f;
        #pragma unroll
        for (int f = 0; f < 8; f++) {
            rmaxA = fmaxf(rmaxA, fmaxf(sacc[f][0], sacc[f][1]));
            rmaxB = fmaxf(rmaxB, fmaxf(sacc[f][2], sacc[f][3]));
        }
        rmaxA = fmaxf(rmaxA, __shfl_xor_sync(0xffffffffu, rmaxA, 1));
        rmaxA = fmaxf(rmaxA, __shfl_xor_sync(0xffffffffu, rmaxA, 2));
        rmaxB = fmaxf(rmaxB, __shfl_xor_sync(0xffffffffu, rmaxB, 1));
        rmaxB = fmaxf(rmaxB, __shfl_xor_sync(0xffffffffu, rmaxB, 2));

        float mnA = fmaxf(mA, rmaxA), mnB = fmaxf(mB, rmaxB);
        float aA = ex2(mA - mnA), aB = ex2(mB - mnB);
        mA = mnA; mB = mnB;

        #pragma unroll
        for (int f = 0; f < 16; f++) {
            oacc[f][0] *= aA; oacc[f][1] *= aA;
            oacc[f][2] *= aB; oacc[f][3] *= aB;
        }

        // ---- phase 2: chunked softmax + PV interleave ----
        float sA = 0.f, sB = 0.f;
        #pragma unroll
        for (int kk = 0; kk < 4; kk++) {
            float p0 = ex2(sacc[2 * kk][0] - mnA);
            float p1 = ex2(sacc[2 * kk][1] - mnA);
            float p2 = ex2(sacc[2 * kk][2] - mnB);
            float p3 = ex2(sacc[2 * kk][3] - mnB);
            float p4 = ex2(sacc[2 * kk + 1][0] - mnA);
            float p5 = ex2(sacc[2 * kk + 1][1] - mnA);
            float p6 = ex2(sacc[2 * kk + 1][2] - mnB);
            float p7 = ex2(sacc[2 * kk + 1][3] - mnB);
            sA += (p0 + p1) + (p4 + p5);
            sB += (p2 + p3) + (p6 + p7);
            u32 ph0 = pack2(p0, p1);
            u32 ph1 = pack2(p2, p3);
            u32 ph2 = pack2(p4, p5);
            u32 ph3 = pack2(p6, p7);
            #pragma unroll
            for (int dp = 0; dp < 8; dp++) {
                u32 voff = swoff(kk * 16 + vkey, dp * 2 + vchh);
                u32 vb0, vb1, vb2, vb3;
                ldm4t(vhb + voff, vb0, vb1, vb2, vb3);
                mma(oacc[2 * dp],     ph0, ph1, ph2, ph3, vb0, vb1);
                mma(oacc[2 * dp + 1], ph0, ph1, ph2, ph3, vb2, vb3);
            }
        }
        lA = fmaf(lA, aA, sA);
        lB = fmaf(lB, aB, sB);

        // signal tile n fully consumed by this thread
        MBAR_ARRIVE(smb + MBE_OFF + b3 * 8);

        if (++b3 == 3) { b3 = 0; par ^= 1; }
    }

    // ---- epilogue: final l reduction over the quad, then store ----
    lA += __shfl_xor_sync(0xffffffffu, lA, 1);
    lA += __shfl_xor_sync(0xffffffffu, lA, 2);
    lB += __shfl_xor_sync(0xffffffffu, lB, 1);
    lB += __shfl_xor_sync(0xffffffffu, lB, 2);
    const float iA = 1.f / lA, iB = 1.f / lB;
    const int ra = wr0 + (lane >> 2);
    const int rb = ra + 8;
    const int cb = 2 * (lane & 3);
    #pragma unroll
    for (int f = 0; f < 16; f++) {
        float2 va; va.x = oacc[f][0] * iA; va.y = oacc[f][1] * iA;
        float2 vb; vb.x = oacc[f][2] * iB; vb.y = oacc[f][3] * iB;
        *(float2*)(Og + (size_t)ra * Dh + f * 8 + cb) = va;
        *(float2*)(Og + (size_t)rb * Dh + f * 8 + cb) = vb;
    }
}

extern "C" void kernel_launch(void* const* d_in, const int* in_sizes, int n_in,
                              void* d_out, int out_size)
{
    const float* q     = (const float*)d_in[0];
    const float* k     = (const float*)d_in[1];
    const float* v     = (const float*)d_in[2];
    const float* scale = (const float*)d_in[3];
    float* out = (float*)d_out;

    dim3 pg(32, NBH);
    prep_kernel<<<pg, NT>>>(k, v);

    cudaFuncSetAttribute(attn_hmma, cudaFuncAttributeMaxDynamicSharedMemorySize, SMEM_BYTES);
    dim3 grid(SEQ / BM, NBH);
    attn_hmma<<<grid, NT, SMEM_BYTES>>>(q, scale, out);
}

// round 15
// speedup vs baseline: 1.0157x; 1.0157x over previous
#include <cuda_runtime.h>
#include <cuda_fp16.h>

typedef unsigned int u32;

#define NT  256
#define BM  128
#define BN  64
#define Dh  128
#define SEQ 2048
#define NIT (SEQ / BN)
#define NBH 64
#define LOG2E 1.44269504088896340736f

// ---- smem byte layout (main kernel) ----
#define QH_OFF 0
#define QL_OFF 32768
#define K_OFF  65536            // 3 bufs x 32768 (hi 16K + lo 16K)
#define V_OFF  163840           // 3 bufs x 16384 (hi only)
#define MB_OFF 212992           // 3 mbarriers x 8B
#define SMEM_BYTES 213248

// ---- global scratch: pre-split f16 K/V images in exact swizzled smem layout ----
__device__ u32 gKsc[NBH * 32 * 8192];    // per (bh,ktile): 16KB hi + 16KB lo
__device__ u32 gVsc[NBH * 32 * 4096];    // per (bh,ktile): 16KB hi

static __device__ __forceinline__ u32 cvta_smem(const void* p) {
    u32 a;
    asm("{ .reg .u64 t; cvta.to.shared.u64 t, %1; cvt.u32.u64 %0, t; }" : "=r"(a) : "l"(p));
    return a;
}
static __device__ __forceinline__ u32 swoff(int row, int ch) {
    return (u32)(row * 256 + ((ch ^ (row & 7)) << 4));
}
static __device__ __forceinline__ float ex2(float x) {
    float y; asm("ex2.approx.f32 %0, %1;" : "=f"(y) : "f"(x)); return y;
}
static __device__ __forceinline__ u32 pack2(float x0, float x1) {
    __half2 h = __floats2half2_rn(x0, x1);
    return *(u32*)&h;
}
static __device__ __forceinline__ void split2(float x0, float x1, u32& hi, u32& lo) {
    __half2 h = __floats2half2_rn(x0, x1);
    float2  b = __half22float2(h);
    __half2 l = __floats2half2_rn(x0 - b.x, x1 - b.y);
    hi = *(u32*)&h; lo = *(u32*)&l;
}

static __device__ __forceinline__ void ldm4(u32 addr, u32& r0, u32& r1, u32& r2, u32& r3) {
    asm volatile("ldmatrix.sync.aligned.m8n8.x4.shared.b16 {%0,%1,%2,%3}, [%4];"
                 : "=r"(r0), "=r"(r1), "=r"(r2), "=r"(r3) : "r"(addr));
}
static __device__ __forceinline__ void ldm4t(u32 addr, u32& r0, u32& r1, u32& r2, u32& r3) {
    asm volatile("ldmatrix.sync.aligned.m8n8.x4.trans.shared.b16 {%0,%1,%2,%3}, [%4];"
                 : "=r"(r0), "=r"(r1), "=r"(r2), "=r"(r3) : "r"(addr));
}
static __device__ __forceinline__ void mma(float* d, u32 a0, u32 a1, u32 a2, u32 a3, u32 b0, u32 b1) {
    asm volatile("mma.sync.aligned.m16n8k16.row.col.f32.f16.f16.f32 "
                 "{%0,%1,%2,%3}, {%4,%5,%6,%7}, {%8,%9}, {%0,%1,%2,%3};"
                 : "+f"(d[0]), "+f"(d[1]), "+f"(d[2]), "+f"(d[3])
                 : "r"(a0), "r"(a1), "r"(a2), "r"(a3), "r"(b0), "r"(b1));
}
#define CP16(dst, src) \
    asm volatile("cp.async.cg.shared.global [%0], [%1], 16;" :: "r"(dst), "l"(src))
// .noinc is load-bearing (round-11 deadlock lesson).
#define CP_MBAR_ARRIVE(mb) \
    asm volatile("cp.async.mbarrier.arrive.noinc.shared.b64 [%0];" :: "r"(mb) : "memory")
#define MBAR_INIT(mb, c) \
    asm volatile("mbarrier.init.shared.b64 [%0], %1;" :: "r"(mb), "r"(c) : "memory")
#define MBAR_WAIT(mb, par) do { \
    u32 _done = 0; \
    while (!_done) { \
        asm volatile("{\n\t.reg .pred p;\n\t" \
            "mbarrier.test_wait.parity.shared.b64 p, [%1], %2;\n\t" \
            "selp.u32 %0, 1, 0, p;\n\t}" \
            : "=r"(_done) : "r"(mb), "r"((u32)(par)) : "memory"); \
    } \
} while (0)

// ============ prep kernel: split K/V f32 -> f16 hi/lo swizzled images ============
__global__ __launch_bounds__(NT, 4)
void prep_kernel(const float* __restrict__ kg, const float* __restrict__ vg)
{
    const int t = blockIdx.x;        // 0..31 (64-row tile)
    const int bh = blockIdx.y;       // 0..63
    const int tid = threadIdx.x;
    const size_t base = (size_t)bh * SEQ * Dh + (size_t)t * 64 * Dh;

    {
        const float* src = kg + base;
        u32* dh = gKsc + (size_t)(bh * 32 + t) * 8192;
        u32* dl = dh + 4096;
        #pragma unroll
        for (int p = 0; p < 4; p++) {
            int idx = tid + p * 256;
            int row = idx >> 4, ch = idx & 15;
            const float* s = src + (size_t)row * Dh + ch * 8;
            float4 a = *(const float4*)s;
            float4 b = *(const float4*)(s + 4);
            u32 h0, l0, h1, l1, h2, l2, h3, l3;
            split2(a.x, a.y, h0, l0); split2(a.z, a.w, h1, l1);
            split2(b.x, b.y, h2, l2); split2(b.z, b.w, h3, l3);
            u32 off = swoff(row, ch) >> 2;
            *(uint4*)(dh + off) = make_uint4(h0, h1, h2, h3);
            *(uint4*)(dl + off) = make_uint4(l0, l1, l2, l3);
        }
    }
    {
        const float* src = vg + base;
        u32* dv = gVsc + (size_t)(bh * 32 + t) * 4096;
        #pragma unroll
        for (int p = 0; p < 4; p++) {
            int idx = tid + p * 256;
            int row = idx >> 4, ch = idx & 15;
            const float* s = src + (size_t)row * Dh + ch * 8;
            float4 a = *(const float4*)s;
            float4 b = *(const float4*)(s + 4);
            u32 off = swoff(row, ch) >> 2;
            *(uint4*)(dv + off) = make_uint4(pack2(a.x, a.y), pack2(a.z, a.w),
                                             pack2(b.x, b.y), pack2(b.z, b.w));
        }
    }
}

// ============ main kernel ============
__global__ __launch_bounds__(NT, 1)
void attn_hmma(const float* __restrict__ qg, const float* __restrict__ scg,
               float* __restrict__ og)
{
    extern __shared__ char sm[];
    const u32 smb = cvta_smem(sm);
    const int tid = threadIdx.x, lane = tid & 31, wid = tid >> 5;

    const int tile = blockIdx.x;
    const int bh   = blockIdx.y;
    const float* Qg = qg + (size_t)bh * SEQ * Dh + (size_t)tile * BM * Dh;
    float*       Og = og + (size_t)bh * SEQ * Dh + (size_t)tile * BM * Dh;
    const float scL = scg[bh] * LOG2E;

    const char* gK = (const char*)(gKsc + (size_t)(bh * 32) * 8192);
    const char* gV = (const char*)(gVsc + (size_t)(bh * 32) * 4096);

    auto issue_tile = [&](int t, int b3) {
        const char* nk = gK + (size_t)t * 32768;
        const char* nv = gV + (size_t)t * 16384;
        u32 kd = smb + K_OFF + b3 * 32768 + tid * 16;
        u32 vd = smb + V_OFF + b3 * 16384 + tid * 16;
        #pragma unroll
        for (int i = 0; i < 8; i++)
            CP16(kd + i * 4096, nk + tid * 16 + i * 4096);
        #pragma unroll
        for (int i = 0; i < 4; i++)
            CP16(vd + i * 4096, nv + tid * 16 + i * 4096);
        CP_MBAR_ARRIVE(smb + MB_OFF + b3 * 8);
    };

    // ---- prologue ----
    if (tid == 0) {
        MBAR_INIT(smb + MB_OFF + 0, NT);
        MBAR_INIT(smb + MB_OFF + 8, NT);
        MBAR_INIT(smb + MB_OFF + 16, NT);
    }
    __syncthreads();

    issue_tile(0, 0);

    // convert Q (scale folded, split) while tile-0 copies fly
    #pragma unroll
    for (int p = 0; p < 8; p++) {
        int idx = tid + p * 256;
        int row = idx >> 4, ch = idx & 15;
        const float* s = Qg + (size_t)row * Dh + ch * 8;
        float4 a = *(const float4*)s;
        float4 b = *(const float4*)(s + 4);
        u32 h0, l0, h1, l1, h2, l2, h3, l3;
        split2(a.x * scL, a.y * scL, h0, l0); split2(a.z * scL, a.w * scL, h1, l1);
        split2(b.x * scL, b.y * scL, h2, l2); split2(b.z * scL, b.w * scL, h3, l3);
        u32 off = swoff(row, ch);
        *(uint4*)(sm + QH_OFF + off) = make_uint4(h0, h1, h2, h3);
        *(uint4*)(sm + QL_OFF + off) = make_uint4(l0, l1, l2, l3);
    }
    __syncthreads();   // Q visible to all warps

    // ---- per-warp state ----
    float oacc[16][4];
    #pragma unroll
    for (int f = 0; f < 16; f++)
        #pragma unroll
        for (int j = 0; j < 4; j++) oacc[f][j] = 0.f;
    float mA = -1e30f, mB = -1e30f, lA = 0.f, lB = 0.f;   // l: lane-partial

    const int wr0 = wid * 16;
    const int qrow = wr0 + (lane & 15);
    const int qchh = lane >> 4;
    const int kn   = (lane & 7) + ((lane >> 4) << 3);
    const int kchh = (lane >> 3) & 1;
    const int vkey = (lane & 7) + (((lane >> 3) & 1) << 3);
    const int vchh = lane >> 4;

    // ---- hoist loop-invariant Q-hi fragments into registers (32 regs) ----
    u32 qh[8][4];
    #pragma unroll
    for (int kk = 0; kk < 8; kk++) {
        u32 qoff = swoff(qrow, kk * 2 + qchh);
        ldm4(smb + QH_OFF + qoff, qh[kk][0], qh[kk][1], qh[kk][2], qh[kk][3]);
    }

    int b3 = 0, par = 0;   // tile n: buf b3 = n%3, parity = (n/3)&1

    #pragma unroll 1
    for (int n = 0; n < NIT; n++) {
        MBAR_WAIT(smb + MB_OFF + b3 * 8, par);

        const int b3n = (b3 == 2) ? 0 : b3 + 1;
        if (n + 1 < NIT) issue_tile(n + 1, b3n);

        const u32 khb = smb + K_OFF + b3 * 32768;
        const u32 klb = khb + 16384;
        const u32 vhb = smb + V_OFF + b3 * 16384;

        // ---- S = (Qh+Ql)(Kh+Kl)^T, 3 products (Qh from registers) ----
        float sacc[8][4];
        #pragma unroll
        for (int f = 0; f < 8; f++)
            #pragma unroll
            for (int j = 0; j < 4; j++) sacc[f][j] = 0.f;

        #pragma unroll
        for (int kk = 0; kk < 8; kk++) {
            u32 qoff = swoff(qrow, kk * 2 + qchh);
            u32 ql0, ql1, ql2, ql3;
            ldm4(smb + QL_OFF + qoff, ql0, ql1, ql2, ql3);
            #pragma unroll
            for (int jp = 0; jp < 4; jp++) {
                u32 koff = swoff(jp * 16 + kn, kk * 2 + kchh);
                u32 kb0, kb1, kb2, kb3, lb0, lb1, lb2, lb3;
                ldm4(khb + koff, kb0, kb1, kb2, kb3);
                ldm4(klb + koff, lb0, lb1, lb2, lb3);
                mma(sacc[jp * 2],     qh[kk][0], qh[kk][1], qh[kk][2], qh[kk][3], kb0, kb1);
                mma(sacc[jp * 2],     qh[kk][0], qh[kk][1], qh[kk][2], qh[kk][3], lb0, lb1);
                mma(sacc[jp * 2],     ql0, ql1, ql2, ql3, kb0, kb1);
                mma(sacc[jp * 2 + 1], qh[kk][0], qh[kk][1], qh[kk][2], qh[kk][3], kb2, kb3);
                mma(sacc[jp * 2 + 1], qh[kk][0], qh[kk][1], qh[kk][2], qh[kk][3], lb2, lb3);
                mma(sacc[jp * 2 + 1], ql0, ql1, ql2, ql3, kb2, kb3);
            }
        }

        // ---- phase 1: max scan, alpha, O-rescale ----
        float rmaxA = -1e30f, rmaxB = -1e30f;
        #pragma unroll
        for (int f = 0; f < 8; f++) {
            rmaxA = fmaxf(rmaxA, fmaxf(sacc[f][0], sacc[f][1]));
            rmaxB = fmaxf(rmaxB, fmaxf(sacc[f][2], sacc[f][3]));
        }
        rmaxA = fmaxf(rmaxA, __shfl_xor_sync(0xffffffffu, rmaxA, 1));
        rmaxA = fmaxf(rmaxA, __shfl_xor_sync(0xffffffffu, rmaxA, 2));
        rmaxB = fmaxf(rmaxB, __shfl_xor_sync(0xffffffffu, rmaxB, 1));
        rmaxB = fmaxf(rmaxB, __shfl_xor_sync(0xffffffffu, rmaxB, 2));

        float mnA = fmaxf(mA, rmaxA), mnB = fmaxf(mB, rmaxB);
        float aA = ex2(mA - mnA), aB = ex2(mB - mnB);
        mA = mnA; mB = mnB;

        #pragma unroll
        for (int f = 0; f < 16; f++) {
            oacc[f][0] *= aA; oacc[f][1] *= aA;
            oacc[f][2] *= aB; oacc[f][3] *= aB;
        }

        // ---- phase 2: chunked softmax + PV interleave ----
        float sA = 0.f, sB = 0.f;
        #pragma unroll
        for (int kk = 0; kk < 4; kk++) {
            float p0 = ex2(sacc[2 * kk][0] - mnA);
            float p1 = ex2(sacc[2 * kk][1] - mnA);
            float p2 = ex2(sacc[2 * kk][2] - mnB);
            float p3 = ex2(sacc[2 * kk][3] - mnB);
            float p4 = ex2(sacc[2 * kk + 1][0] - mnA);
            float p5 = ex2(sacc[2 * kk + 1][1] - mnA);
            float p6 = ex2(sacc[2 * kk + 1][2] - mnB);
            float p7 = ex2(sacc[2 * kk + 1][3] - mnB);
            sA += (p0 + p1) + (p4 + p5);
            sB += (p2 + p3) + (p6 + p7);
            u32 ph0 = pack2(p0, p1);
            u32 ph1 = pack2(p2, p3);
            u32 ph2 = pack2(p4, p5);
            u32 ph3 = pack2(p6, p7);
            #pragma unroll
            for (int dp = 0; dp < 8; dp++) {
                u32 voff = swoff(kk * 16 + vkey, dp * 2 + vchh);
                u32 vb0, vb1, vb2, vb3;
                ldm4t(vhb + voff, vb0, vb1, vb2, vb3);
                mma(oacc[2 * dp],     ph0, ph1, ph2, ph3, vb0, vb1);
                mma(oacc[2 * dp + 1], ph0, ph1, ph2, ph3, vb2, vb3);
            }
        }
        lA = fmaf(lA, aA, sA);
        lB = fmaf(lB, aB, sB);

        if (++b3 == 3) { b3 = 0; par ^= 1; }
    }

    // ---- epilogue: final l reduction over the quad, then store ----
    lA += __shfl_xor_sync(0xffffffffu, lA, 1);
    lA += __shfl_xor_sync(0xffffffffu, lA, 2);
    lB += __shfl_xor_sync(0xffffffffu, lB, 1);
    lB += __shfl_xor_sync(0xffffffffu, lB, 2);
    const float iA = 1.f / lA, iB = 1.f / lB;
    const int ra = wr0 + (lane >> 2);
    const int rb = ra + 8;
    const int cb = 2 * (lane & 3);
    #pragma unroll
    for (int f = 0; f < 16; f++) {
        float2 va; va.x = oacc[f][0] * iA; va.y = oacc[f][1] * iA;
        float2 vb; vb.x = oacc[f][2] * iB; vb.y = oacc[f][3] * iB;
        *(float2*)(Og + (size_t)ra * Dh + f * 8 + cb) = va;
        *(float2*)(Og + (size_t)rb * Dh + f * 8 + cb) = vb;
    }
}

extern "C" void kernel_launch(void* const* d_in, const int* in_sizes, int n_in,
                              void* d_out, int out_size)
{
    const float* q     = (const float*)d_in[0];
    const float* k     = (const float*)d_in[1];
    const float* v     = (const float*)d_in[2];
    const float* scale = (const float*)d_in[3];
    float* out = (float*)d_out;

    dim3 pg(32, NBH);
    prep_kernel<<<pg, NT>>>(k, v);

    cudaFuncSetAttribute(attn_hmma, cudaFuncAttributeMaxDynamicSharedMemorySize, SMEM_BYTES);
    dim3 grid(SEQ / BM, NBH);
    attn_hmma<<<grid, NT, SMEM_BYTES>>>(q, scale, out);
}

// round 16
// speedup vs baseline: 1.0172x; 1.0014x over previous
#include <cuda_runtime.h>
#include <cuda_fp16.h>

typedef unsigned int u32;

#define NT  256
#define BM  128
#define BN  64
#define Dh  128
#define SEQ 2048
#define NIT (SEQ / BN)
#define NBH 64
#define LOG2E 1.44269504088896340736f

// ---- smem byte layout (main kernel) ----
#define QH_OFF 0
#define QL_OFF 32768
#define K_OFF  65536            // 3 bufs x 32768 (hi 16K + lo 16K)
#define V_OFF  163840           // 3 bufs x 16384 (hi only)
#define MB_OFF 212992           // 3 mbarriers x 8B
#define SMEM_BYTES 213248

// ---- global scratch: pre-split f16 K/V images in exact swizzled smem layout ----
__device__ u32 gKsc[NBH * 32 * 8192];    // per (bh,ktile): 16KB hi + 16KB lo
__device__ u32 gVsc[NBH * 32 * 4096];    // per (bh,ktile): 16KB hi

static __device__ __forceinline__ u32 cvta_smem(const void* p) {
    u32 a;
    asm("{ .reg .u64 t; cvta.to.shared.u64 t, %1; cvt.u32.u64 %0, t; }" : "=r"(a) : "l"(p));
    return a;
}
static __device__ __forceinline__ u32 swoff(int row, int ch) {
    return (u32)(row * 256 + ((ch ^ (row & 7)) << 4));
}
static __device__ __forceinline__ float ex2(float x) {
    float y; asm("ex2.approx.f32 %0, %1;" : "=f"(y) : "f"(x)); return y;
}
static __device__ __forceinline__ u32 pack2(float x0, float x1) {
    __half2 h = __floats2half2_rn(x0, x1);
    return *(u32*)&h;
}
static __device__ __forceinline__ void split2(float x0, float x1, u32& hi, u32& lo) {
    __half2 h = __floats2half2_rn(x0, x1);
    float2  b = __half22float2(h);
    __half2 l = __floats2half2_rn(x0 - b.x, x1 - b.y);
    hi = *(u32*)&h; lo = *(u32*)&l;
}

static __device__ __forceinline__ void ldm4(u32 addr, u32& r0, u32& r1, u32& r2, u32& r3) {
    asm volatile("ldmatrix.sync.aligned.m8n8.x4.shared.b16 {%0,%1,%2,%3}, [%4];"
                 : "=r"(r0), "=r"(r1), "=r"(r2), "=r"(r3) : "r"(addr));
}
static __device__ __forceinline__ void ldm4t(u32 addr, u32& r0, u32& r1, u32& r2, u32& r3) {
    asm volatile("ldmatrix.sync.aligned.m8n8.x4.trans.shared.b16 {%0,%1,%2,%3}, [%4];"
                 : "=r"(r0), "=r"(r1), "=r"(r2), "=r"(r3) : "r"(addr));
}
static __device__ __forceinline__ void mma(float* d, u32 a0, u32 a1, u32 a2, u32 a3, u32 b0, u32 b1) {
    asm volatile("mma.sync.aligned.m16n8k16.row.col.f32.f16.f16.f32 "
                 "{%0,%1,%2,%3}, {%4,%5,%6,%7}, {%8,%9}, {%0,%1,%2,%3};"
                 : "+f"(d[0]), "+f"(d[1]), "+f"(d[2]), "+f"(d[3])
                 : "r"(a0), "r"(a1), "r"(a2), "r"(a3), "r"(b0), "r"(b1));
}
#define CP16(dst, src) \
    asm volatile("cp.async.cg.shared.global [%0], [%1], 16;" :: "r"(dst), "l"(src))
// .noinc is load-bearing (round-11 deadlock lesson).
#define CP_MBAR_ARRIVE(mb) \
    asm volatile("cp.async.mbarrier.arrive.noinc.shared.b64 [%0];" :: "r"(mb) : "memory")
#define MBAR_INIT(mb, c) \
    asm volatile("mbarrier.init.shared.b64 [%0], %1;" :: "r"(mb), "r"(c) : "memory")
// try_wait = HW-sleep (wakeup ~60cyc) vs test_wait polling (~149cyc/poll)
#define MBAR_WAIT(mb, par) do { \
    asm volatile("{\n\t.reg .pred P1;\n\t" \
        "WL%=:\n\t" \
        "mbarrier.try_wait.parity.shared.b64 P1, [%0], %1, 0x989680;\n\t" \
        "@P1 bra.uni WD%=;\n\t" \
        "bra.uni WL%=;\n\t" \
        "WD%=:\n\t}" \
        :: "r"(mb), "r"((u32)(par)) : "memory"); \
} while (0)

// ============ prep kernel: split K/V f32 -> f16 hi/lo swizzled images ============
__global__ __launch_bounds__(NT, 4)
void prep_kernel(const float* __restrict__ kg, const float* __restrict__ vg)
{
    const int t = blockIdx.x;        // 0..31 (64-row tile)
    const int bh = blockIdx.y;       // 0..63
    const int tid = threadIdx.x;
    const size_t base = (size_t)bh * SEQ * Dh + (size_t)t * 64 * Dh;

    {
        const float* src = kg + base;
        u32* dh = gKsc + (size_t)(bh * 32 + t) * 8192;
        u32* dl = dh + 4096;
        #pragma unroll
        for (int p = 0; p < 4; p++) {
            int idx = tid + p * 256;
            int row = idx >> 4, ch = idx & 15;
            const float* s = src + (size_t)row * Dh + ch * 8;
            float4 a = *(const float4*)s;
            float4 b = *(const float4*)(s + 4);
            u32 h0, l0, h1, l1, h2, l2, h3, l3;
            split2(a.x, a.y, h0, l0); split2(a.z, a.w, h1, l1);
            split2(b.x, b.y, h2, l2); split2(b.z, b.w, h3, l3);
            u32 off = swoff(row, ch) >> 2;
            *(uint4*)(dh + off) = make_uint4(h0, h1, h2, h3);
            *(uint4*)(dl + off) = make_uint4(l0, l1, l2, l3);
        }
    }
    {
        const float* src = vg + base;
        u32* dv = gVsc + (size_t)(bh * 32 + t) * 4096;
        #pragma unroll
        for (int p = 0; p < 4; p++) {
            int idx = tid + p * 256;
            int row = idx >> 4, ch = idx & 15;
            const float* s = src + (size_t)row * Dh + ch * 8;
            float4 a = *(const float4*)s;
            float4 b = *(const float4*)(s + 4);
            u32 off = swoff(row, ch) >> 2;
            *(uint4*)(dv + off) = make_uint4(pack2(a.x, a.y), pack2(a.z, a.w),
                                             pack2(b.x, b.y), pack2(b.z, b.w));
        }
    }
}

// ============ main kernel ============
__global__ __launch_bounds__(NT, 1)
void attn_hmma(const float* __restrict__ qg, const float* __restrict__ scg,
               float* __restrict__ og)
{
    extern __shared__ char sm[];
    const u32 smb = cvta_smem(sm);
    const int tid = threadIdx.x, lane = tid & 31, wid = tid >> 5;

    const int tile = blockIdx.x;
    const int bh   = blockIdx.y;
    const float* Qg = qg + (size_t)bh * SEQ * Dh + (size_t)tile * BM * Dh;
    float*       Og = og + (size_t)bh * SEQ * Dh + (size_t)tile * BM * Dh;
    const float scL = scg[bh] * LOG2E;

    const char* gK = (const char*)(gKsc + (size_t)(bh * 32) * 8192);
    const char* gV = (const char*)(gVsc + (size_t)(bh * 32) * 4096);

    auto issue_tile = [&](int t, int b3) {
        const char* nk = gK + (size_t)t * 32768;
        const char* nv = gV + (size_t)t * 16384;
        u32 kd = smb + K_OFF + b3 * 32768 + tid * 16;
        u32 vd = smb + V_OFF + b3 * 16384 + tid * 16;
        #pragma unroll
        for (int i = 0; i < 8; i++)
            CP16(kd + i * 4096, nk + tid * 16 + i * 4096);
        #pragma unroll
        for (int i = 0; i < 4; i++)
            CP16(vd + i * 4096, nv + tid * 16 + i * 4096);
        CP_MBAR_ARRIVE(smb + MB_OFF + b3 * 8);
    };

    // ---- prologue ----
    if (tid == 0) {
        MBAR_INIT(smb + MB_OFF + 0, NT);
        MBAR_INIT(smb + MB_OFF + 8, NT);
        MBAR_INIT(smb + MB_OFF + 16, NT);
    }
    __syncthreads();

    issue_tile(0, 0);

    // convert Q (scale folded, split) while tile-0 copies fly
    #pragma unroll
    for (int p = 0; p < 8; p++) {
        int idx = tid + p * 256;
        int row = idx >> 4, ch = idx & 15;
        const float* s = Qg + (size_t)row * Dh + ch * 8;
        float4 a = *(const float4*)s;
        float4 b = *(const float4*)(s + 4);
        u32 h0, l0, h1, l1, h2, l2, h3, l3;
        split2(a.x * scL, a.y * scL, h0, l0); split2(a.z * scL, a.w * scL, h1, l1);
        split2(b.x * scL, b.y * scL, h2, l2); split2(b.z * scL, b.w * scL, h3, l3);
        u32 off = swoff(row, ch);
        *(uint4*)(sm + QH_OFF + off) = make_uint4(h0, h1, h2, h3);
        *(uint4*)(sm + QL_OFF + off) = make_uint4(l0, l1, l2, l3);
    }
    __syncthreads();   // Q visible to all warps

    // ---- per-warp state ----
    float oacc[16][4];
    #pragma unroll
    for (int f = 0; f < 16; f++)
        #pragma unroll
        for (int j = 0; j < 4; j++) oacc[f][j] = 0.f;
    float mA = -1e30f, mB = -1e30f, lA = 0.f, lB = 0.f;   // l: lane-partial

    const int wr0 = wid * 16;
    const int qrow = wr0 + (lane & 15);
    const int qchh = lane >> 4;
    const int kn   = (lane & 7) + ((lane >> 4) << 3);
    const int kchh = (lane >> 3) & 1;
    const int vkey = (lane & 7) + (((lane >> 3) & 1) << 3);
    const int vchh = lane >> 4;

    // ---- hoist loop-invariant Q-hi fragments into registers (32 regs) ----
    u32 qh[8][4];
    #pragma unroll
    for (int kk = 0; kk < 8; kk++) {
        u32 qoff = swoff(qrow, kk * 2 + qchh);
        ldm4(smb + QH_OFF + qoff, qh[kk][0], qh[kk][1], qh[kk][2], qh[kk][3]);
    }

    int b3 = 0, par = 0;   // tile n: buf b3 = n%3, parity = (n/3)&1

    #pragma unroll 1
    for (int n = 0; n < NIT; n++) {
        MBAR_WAIT(smb + MB_OFF + b3 * 8, par);

        const u32 khb = smb + K_OFF + b3 * 32768;
        const u32 klb = khb + 16384;
        const u32 vhb = smb + V_OFF + b3 * 16384;

        // ---- S = (Qh+Ql)(Kh+Kl)^T, 3 products (Qh from registers) ----
        float sacc[8][4];
        #pragma unroll
        for (int f = 0; f < 8; f++)
            #pragma unroll
            for (int j = 0; j < 4; j++) sacc[f][j] = 0.f;

        #pragma unroll
        for (int kk = 0; kk < 8; kk++) {
            u32 qoff = swoff(qrow, kk * 2 + qchh);
            u32 ql0, ql1, ql2, ql3;
            ldm4(smb + QL_OFF + qoff, ql0, ql1, ql2, ql3);
            #pragma unroll
            for (int jp = 0; jp < 4; jp++) {
                u32 koff = swoff(jp * 16 + kn, kk * 2 + kchh);
                u32 kb0, kb1, kb2, kb3, lb0, lb1, lb2, lb3;
                ldm4(khb + koff, kb0, kb1, kb2, kb3);
                ldm4(klb + koff, lb0, lb1, lb2, lb3);
                mma(sacc[jp * 2],     qh[kk][0], qh[kk][1], qh[kk][2], qh[kk][3], kb0, kb1);
                mma(sacc[jp * 2],     qh[kk][0], qh[kk][1], qh[kk][2], qh[kk][3], lb0, lb1);
                mma(sacc[jp * 2],     ql0, ql1, ql2, ql3, kb0, kb1);
                mma(sacc[jp * 2 + 1], qh[kk][0], qh[kk][1], qh[kk][2], qh[kk][3], kb2, kb3);
                mma(sacc[jp * 2 + 1], qh[kk][0], qh[kk][1], qh[kk][2], qh[kk][3], lb2, lb3);
                mma(sacc[jp * 2 + 1], ql0, ql1, ql2, ql3, kb2, kb3);
            }
        }

        // ---- issue copies for tile n+1 (moved off the critical head; still
        // a full softmax+PV phase ahead of its consumption at iter n+1) ----
        const int b3n = (b3 == 2) ? 0 : b3 + 1;
        if (n + 1 < NIT) issue_tile(n + 1, b3n);

        // ---- phase 1: max scan, alpha, O-rescale ----
        float rmaxA = -1e30f, rmaxB = -1e30f;
        #pragma unroll
        for (int f = 0; f < 8; f++) {
            rmaxA = fmaxf(rmaxA, fmaxf(sacc[f][0], sacc[f][1]));
            rmaxB = fmaxf(rmaxB, fmaxf(sacc[f][2], sacc[f][3]));
        }
        rmaxA = fmaxf(rmaxA, __shfl_xor_sync(0xffffffffu, rmaxA, 1));
        rmaxA = fmaxf(rmaxA, __shfl_xor_sync(0xffffffffu, rmaxA, 2));
        rmaxB = fmaxf(rmaxB, __shfl_xor_sync(0xffffffffu, rmaxB, 1));
        rmaxB = fmaxf(rmaxB, __shfl_xor_sync(0xffffffffu, rmaxB, 2));

        float mnA = fmaxf(mA, rmaxA), mnB = fmaxf(mB, rmaxB);
        float aA = ex2(mA - mnA), aB = ex2(mB - mnB);
        mA = mnA; mB = mnB;

        #pragma unroll
        for (int f = 0; f < 16; f++) {
            oacc[f][0] *= aA; oacc[f][1] *= aA;
            oacc[f][2] *= aB; oacc[f][3] *= aB;
        }

        // ---- phase 2: chunked softmax + PV interleave ----
        float sA = 0.f, sB = 0.f;
        #pragma unroll
        for (int kk = 0; kk < 4; kk++) {
            float p0 = ex2(sacc[2 * kk][0] - mnA);
            float p1 = ex2(sacc[2 * kk][1] - mnA);
            float p2 = ex2(sacc[2 * kk][2] - mnB);
            float p3 = ex2(sacc[2 * kk][3] - mnB);
            float p4 = ex2(sacc[2 * kk + 1][0] - mnA);
            float p5 = ex2(sacc[2 * kk + 1][1] - mnA);
            float p6 = ex2(sacc[2 * kk + 1][2] - mnB);
            float p7 = ex2(sacc[2 * kk + 1][3] - mnB);
            sA += (p0 + p1) + (p4 + p5);
            sB += (p2 + p3) + (p6 + p7);
            u32 ph0 = pack2(p0, p1);
            u32 ph1 = pack2(p2, p3);
            u32 ph2 = pack2(p4, p5);
            u32 ph3 = pack2(p6, p7);
            #pragma unroll
            for (int dp = 0; dp < 8; dp++) {
                u32 voff = swoff(kk * 16 + vkey, dp * 2 + vchh);
                u32 vb0, vb1, vb2, vb3;
                ldm4t(vhb + voff, vb0, vb1, vb2, vb3);
                mma(oacc[2 * dp],     ph0, ph1, ph2, ph3, vb0, vb1);
                mma(oacc[2 * dp + 1], ph0, ph1, ph2, ph3, vb2, vb3);
            }
        }
        lA = fmaf(lA, aA, sA);
        lB = fmaf(lB, aB, sB);

        if (++b3 == 3) { b3 = 0; par ^= 1; }
    }

    // ---- epilogue: final l reduction over the quad, then store ----
    lA += __shfl_xor_sync(0xffffffffu, lA, 1);
    lA += __shfl_xor_sync(0xffffffffu, lA, 2);
    lB += __shfl_xor_sync(0xffffffffu, lB, 1);
    lB += __shfl_xor_sync(0xffffffffu, lB, 2);
    const float iA = 1.f / lA, iB = 1.f / lB;
    const int ra = wr0 + (lane >> 2);
    const int rb = ra + 8;
    const int cb = 2 * (lane & 3);
    #pragma unroll
    for (int f = 0; f < 16; f++) {
        float2 va; va.x = oacc[f][0] * iA; va.y = oacc[f][1] * iA;
        float2 vb; vb.x = oacc[f][2] * iB; vb.y = oacc[f][3] * iB;
        *(float2*)(Og + (size_t)ra * Dh + f * 8 + cb) = va;
        *(float2*)(Og + (size_t)rb * Dh + f * 8 + cb) = vb;
    }
}

extern "C" void kernel_launch(void* const* d_in, const int* in_sizes, int n_in,
                              void* d_out, int out_size)
{
    const float* q     = (const float*)d_in[0];
    const float* k     = (const float*)d_in[1];
    const float* v     = (const float*)d_in[2];
    const float* scale = (const float*)d_in[3];
    float* out = (float*)d_out;

    dim3 pg(32, NBH);
    prep_kernel<<<pg, NT>>>(k, v);

    cudaFuncSetAttribute(attn_hmma, cudaFuncAttributeMaxDynamicSharedMemorySize, SMEM_BYTES);
    dim3 grid(SEQ / BM, NBH);
    attn_hmma<<<grid, NT, SMEM_BYTES>>>(q, scale, out);
}